// round 15
// baseline (speedup 1.0000x reference)
#include <cuda_runtime.h>

#define NN 128
#define TRI (NN * (NN + 1) / 2)   // 8256 cells per triangular table

__device__ __forceinline__ int triRow(int a) {
    return a * (2 * NN - a + 1) / 2;   // index of cell (a,a) in triangular packing
}

#define NEGC    (-9999.0f)
#define THRESHC (-9000.0f)

__device__ __forceinline__ int ld_acq_shared(const int* p) {
    int v;
    unsigned a = (unsigned)__cvta_generic_to_shared(p);
    asm volatile("ld.acquire.cta.shared.b32 %0, [%1];" : "=r"(v) : "r"(a) : "memory");
    return v;
}
__device__ __forceinline__ void st_rel_shared(int* p, int v) {
    unsigned a = (unsigned)__cvta_generic_to_shared(p);
    asm volatile("st.release.cta.shared.b32 [%0], %1;" :: "r"(a), "r"(v) : "memory");
}

// Chart storage: one float4 per triangular cell:
//   Q[c] = (T00[c], T11[c], T10[c], T01[c])
// flags[c] = 1 once cell c is written (diag cells pre-set).

// One DP step for span width k, G lanes cooperating per span.
// Sync: program order covers intra-warp deps; only the last group of each
// warp polls its cross-warp flag, except at G-transition steps (chkAll).
// Spin: whole-warp poll with immediate nanosleep (R10/R12-proven optimum).
// LATRED: single-pass paired argmax reduce (half the serial shuffle depth)
// for the chain-latency-bound G16/G32 tail; two-pass elsewhere.
template<int G, bool LATRED>
__device__ __forceinline__ void step_body(
    float4* __restrict__ Q, int* __restrict__ flags,
    const float* __restrict__ vin,
    float* __restrict__ outS, float* __restrict__ outB,
    int has_bt, int k, int tid, bool chkAll)
{
    const int nspans = NN - k;
    // whole-warp early out (uniform across the warp since G divides 32)
    if (((tid & ~31) / G) >= nspans) return;

    const int gid_raw = tid / G;
    const int lig = tid % G;
    const bool lead = (lig == 0) && (gid_raw < nspans);
    const int i = min(gid_raw, nspans - 1);   // clamp dup groups (writes gated by lead)
    const int j = i + k;
    const int rpi = triRow(i);

    // ---- prefetch arc scores + setup BEFORE the wait (off the flag chain) ----
    const float vL = vin[j * NN + i];   // left arc  (head j)
    const float vR = vin[i * NN + j];   // right arc (head i)

    int m  = lig + 1;                   // lane lig handles m = lig+1, lig+1+G, ...
    int q0 = i + m;
    const int A0  = triRow(q0) + (j - q0);                 // tri(q, j)
    const int dA0 = G * (NN - 1 - q0) - (G * (G - 1)) / 2; // A(m+G) - A(m)
    const char* Qb = (const char*)Q;
    int A16   = A0 * 16;
    int B16   = A16 + (NN - 1 - q0) * 16;   // tri(q+1, j) * 16
    int dA16  = dA0 * 16;
    int idx16 = (rpi + m) * 16;             // tri(i, q) * 16

    // ---- gate: poll only what program order can't prove (R12-proven spin) ----
    {
        const bool lastg = (((tid & 31) / G) == (32 / G - 1));
        const bool needs = (gid_raw < nspans) && (chkAll || lastg);
        const int f1 = rpi + (k - 1);              // tri(i, j-1)
        const int f2 = rpi + (NN - i) + (k - 1);   // tri(i+1, j)
        int r = 1;
        if (needs) {
            r = ld_acq_shared(flags + f2);
            if (chkAll) r &= ld_acq_shared(flags + f1);
        }
        while (!__all_sync(0xffffffffu, r)) {
            __nanosleep(32);
            r = 1;
            if (needs) {
                r = ld_acq_shared(flags + f2);
                if (chkAll) r &= ld_acq_shared(flags + f1);
            }
        }
    }

    const float NINF = __int_as_float(0xff800000);
    float v00 = NINF, v10 = NINF, v01 = NINF, v11 = NINF;
    int   m00 = NN,   m10 = NN,   m01 = NN,   m11 = NN;

    #pragma unroll 2
    for (; m < k; m += G) {
        const float4 qr = *(const float4*)(Qb + idx16);    // (T00,T11,T10,T01)[i][q]
        const float2 qa = *(const float2*)(Qb + A16);      // (T00,T11)[q][j]
        const float  qb = *(const float*)(Qb + B16 + 12);  // T01[q+1][j]
        const float base = qr.y + qb;
        // preserve reference rounding order: ((s11+s01)+v)+5.0
        float a0  = (base + vL) + 5.0f;
        float a1  = (base + vR) + 5.0f;
        float c01 = qr.w + qa.x;    // T01[i][q] + T00[q][j]
        float c11 = qr.z + qa.y;    // T10[i][q] + T11[q][j]
        if (a0  > v00) { v00 = a0;  m00 = m; }
        if (a1  > v10) { v10 = a1;  m10 = m; }
        if (c01 > v01) { v01 = c01; m01 = m; }
        if (c11 > v11) { v11 = c11; m11 = m; }
        A16 += dA16; B16 += dA16 - 16 * G; dA16 -= 16 * G * G; idx16 += 16 * G;
    }

    if (G > 1) {
        if (LATRED) {
            // single-pass paired butterflies: half the serial shuffle depth
            #pragma unroll
            for (int off = G / 2; off; off >>= 1) {
                float ov; int om;
                ov = __shfl_xor_sync(0xffffffffu, v00, off);
                om = __shfl_xor_sync(0xffffffffu, m00, off);
                if (ov > v00 || (ov == v00 && om < m00)) { v00 = ov; m00 = om; }
                ov = __shfl_xor_sync(0xffffffffu, v10, off);
                om = __shfl_xor_sync(0xffffffffu, m10, off);
                if (ov > v10 || (ov == v10 && om < m10)) { v10 = ov; m10 = om; }
                ov = __shfl_xor_sync(0xffffffffu, v01, off);
                om = __shfl_xor_sync(0xffffffffu, m01, off);
                if (ov > v01 || (ov == v01 && om < m01)) { v01 = ov; m01 = om; }
                ov = __shfl_xor_sync(0xffffffffu, v11, off);
                om = __shfl_xor_sync(0xffffffffu, m11, off);
                if (ov > v11 || (ov == v11 && om < m11)) { v11 = ov; m11 = om; }
            }
        } else {
            // two-pass: value-only max butterflies, then min-index among ties
            const float o00 = v00, o10 = v10, o01 = v01, o11 = v11;
            #pragma unroll
            for (int off = G / 2; off; off >>= 1) {
                v00 = fmaxf(v00, __shfl_xor_sync(0xffffffffu, v00, off));
                v10 = fmaxf(v10, __shfl_xor_sync(0xffffffffu, v10, off));
                v01 = fmaxf(v01, __shfl_xor_sync(0xffffffffu, v01, off));
                v11 = fmaxf(v11, __shfl_xor_sync(0xffffffffu, v11, off));
            }
            m00 = (o00 == v00) ? m00 : 0x7fffffff;
            m10 = (o10 == v10) ? m10 : 0x7fffffff;
            m01 = (o01 == v01) ? m01 : 0x7fffffff;
            m11 = (o11 == v11) ? m11 : 0x7fffffff;
            #pragma unroll
            for (int off = G / 2; off; off >>= 1) {
                m00 = min(m00, __shfl_xor_sync(0xffffffffu, m00, off));
                m10 = min(m10, __shfl_xor_sync(0xffffffffu, m10, off));
                m01 = min(m01, __shfl_xor_sync(0xffffffffu, m01, off));
                m11 = min(m11, __shfl_xor_sync(0xffffffffu, m11, off));
            }
        }
    }

    if (lead) {
        // ---- m = 0 candidates (share loads with the reference quirk) ----
        const float t11_ii = ((const float4*)Qb)[rpi].y;                   // T11[i][i]
        const float t01_b  = *(const float*)(Qb + (rpi + (NN - i) + (k - 1)) * 16 + 12); // T01[i+1][j]
        const float base0 = t11_ii + t01_b;
        float a0_0 = (base0 + vL) + 5.0f;
        float a1_0 = (base0 + vR) + 5.0f;
        // m=0 is the smallest split: wins value ties (first occurrence)
        if (a0_0 >= v00) { v00 = a0_0; m00 = 0; }
        if (a1_0 >= v10) { v10 = a1_0; m10 = 0; }

        // quirk: (0,1) at q=i sees the (0,0) cell after ONLY the q=i update
        float p000 = fmaxf(a0_0, NEGC);
        const float part00 = (p000 > THRESHC) ? p000 : NEGC;
        if (part00 > v01 || (part00 == v01 && 0 < m01)) { v01 = part00; m01 = 0; }
        // quirk: (1,1) at q=j sees the fully updated (1,0) cell
        const float new10 = (v10 > THRESHC) ? v10 : NEGC;
        if (new10 > v11) { v11 = new10; m11 = k; }

        const float s00 = (v00 > THRESHC) ? v00 : NEGC;
        const float s10 = (v10 > THRESHC) ? v10 : NEGC;
        const float s01 = (v01 > THRESHC) ? v01 : NEGC;
        const float s11 = (v11 > THRESHC) ? v11 : NEGC;

        // ---- publish FIRST (this is the dependency chain) ----
        const int tij = rpi + k;   // tri(i, j)
        Q[tij] = make_float4(s00, s11, s10, s01);
        st_rel_shared(flags + tij, 1);      // release orders the STS above

        // ---- outputs AFTER the release (off the chain), vectorized ----
        const int t00 = (v00 > THRESHC) ? (i + m00) : 0;
        const int t10 = (v10 > THRESHC) ? (i + m10) : 0;
        const int t01 = (v01 > THRESHC) ? (i + m01) : 0;
        const int t11 = (v11 > THRESHC) ? (i + m11) : 0;

        const size_t o = ((size_t)(i * NN + j)) * 4;
        *(float4*)(outS + o) = make_float4(s00, s01, s10, s11);
        if (has_bt) {
            *(float4*)(outB + o) =
                make_float4((float)t00, (float)t01, (float)t10, (float)t11);
        }
    }
}

__global__ void __launch_bounds__(512, 1)
eisner_kernel(const float* __restrict__ vin_all,
              float* __restrict__ out,
              int has_bt, int bt_off)
{
    extern __shared__ float sm[];
    float4* Q = (float4*)sm;                    // TRI cells x 16 B = 132096 B
    int* flags = (int*)(sm + 4 * TRI);          // TRI x 4 B = 33024 B

    const int b = blockIdx.x;
    const float* __restrict__ vin = vin_all + (size_t)b * NN * NN;
    float* __restrict__ outS = out + (size_t)b * NN * NN * 4;
    float* __restrict__ outB = out + (size_t)bt_off + (size_t)b * NN * NN * 4;

    const int tid = threadIdx.x;

    // ---- init (vectorized): all cells NEG, diag = 0; flags 0, diag 1 ----
    {
        float4* sm4 = (float4*)sm;
        const float4 negv = make_float4(NEGC, NEGC, NEGC, NEGC);
        for (int t = tid; t < TRI; t += blockDim.x) sm4[t] = negv;
        int4* fl4 = (int4*)flags;
        const int4 z4 = make_int4(0, 0, 0, 0);
        for (int t = tid; t < TRI / 4; t += blockDim.x) fl4[t] = z4;
    }
    __syncthreads();
    for (int i = tid; i < NN; i += blockDim.x) {
        int d = triRow(i);
        Q[d] = make_float4(0.0f, 0.0f, 0.0f, 0.0f);
        flags[d] = 1;
    }
    // ---- init output (vectorized): scores = NEG, backtrace = 0 ----
    {
        float4* oS4 = (float4*)outS;
        const float4 negv = make_float4(NEGC, NEGC, NEGC, NEGC);
        for (int t = tid; t < NN * NN; t += blockDim.x) oS4[t] = negv;
        if (has_bt) {
            float4* oB4 = (float4*)outB;
            const float4 zv = make_float4(0.0f, 0.0f, 0.0f, 0.0f);
            for (int t = tid; t < NN * NN; t += blockDim.x) oB4[t] = zv;
        }
        // diagonal score cells = 0
        for (int i = tid; i < NN; i += blockDim.x)
            oS4[i * NN + i] = make_float4(0.0f, 0.0f, 0.0f, 0.0f);
    }
    __syncthreads();   // single block-wide barrier; rest is dataflow-synced

    // G policy: k<=12:G1, <=24:G2, <=64:G4, <=96:G8, <=112:G16, else G32.
    // chkAll at G-transition steps (group->warp mapping changed there).
    // LATRED only in the chain-latency-bound G16/G32 tail.
    for (int k = 1; k < NN; ++k) {
        if (k <= 12)
            step_body<1,  false>(Q, flags, vin, outS, outB, has_bt, k, tid, false);
        else if (k <= 24)
            step_body<2,  false>(Q, flags, vin, outS, outB, has_bt, k, tid, k == 13);
        else if (k <= 64)
            step_body<4,  false>(Q, flags, vin, outS, outB, has_bt, k, tid, k == 25);
        else if (k <= 96)
            step_body<8,  false>(Q, flags, vin, outS, outB, has_bt, k, tid, k == 65);
        else if (k <= 112)
            step_body<16, true >(Q, flags, vin, outS, outB, has_bt, k, tid, k == 97);
        else
            step_body<32, true >(Q, flags, vin, outS, outB, has_bt, k, tid, k == 113);
    }
}

extern "C" void kernel_launch(void* const* d_in, const int* in_sizes, int n_in,
                              void* d_out, int out_size)
{
    const float* vin = (const float*)d_in[0];
    float* out = (float*)d_out;
    const int B = in_sizes[0] / (NN * NN);          // 64
    const int score_elems = B * NN * NN * 4;        // scores region size
    const int has_bt = (out_size >= 2 * score_elems) ? 1 : 0;

    const int smem_bytes = 4 * TRI * sizeof(float) + TRI * sizeof(int); // 165120 B
    cudaFuncSetAttribute(eisner_kernel,
                         cudaFuncAttributeMaxDynamicSharedMemorySize, smem_bytes);
    eisner_kernel<<<B, 512, smem_bytes>>>(vin, out, has_bt, score_elems);
}

// round 16
// speedup vs baseline: 1.7609x; 1.7609x over previous
#include <cuda_runtime.h>

#define NN 128
#define TRI (NN * (NN + 1) / 2)   // 8256 cells per triangular table

__device__ __forceinline__ int triRow(int a) {
    return a * (2 * NN - a + 1) / 2;   // index of cell (a,a) in triangular packing
}

#define NEGC    (-9999.0f)
#define THRESHC (-9000.0f)

__device__ __forceinline__ int ld_acq_shared(const int* p) {
    int v;
    unsigned a = (unsigned)__cvta_generic_to_shared(p);
    asm volatile("ld.acquire.cta.shared.b32 %0, [%1];" : "=r"(v) : "r"(a) : "memory");
    return v;
}
__device__ __forceinline__ void st_rel_shared(int* p, int v) {
    unsigned a = (unsigned)__cvta_generic_to_shared(p);
    asm volatile("st.release.cta.shared.b32 [%0], %1;" :: "r"(a), "r"(v) : "memory");
}

// Chart storage: one float4 per triangular cell:
//   Q[c] = (T00[c], T11[c], T10[c], T01[c])
// flags[c] = 1 once cell c is written (diag cells pre-set).

// One DP step for span width k, G lanes cooperating per span.
// Sync: program order covers intra-warp deps; only the last group of each
// warp polls its cross-warp flag, except at G-transition steps (CHK).
// Spin: whole-warp poll with immediate nanosleep (R10/R12-proven optimum).
// Reduce: two-pass (value max, then min-index among ties) — proven form.
template<int G, bool CHK>
__device__ __forceinline__ void step_body(
    float4* __restrict__ Q, int* __restrict__ flags,
    const float* __restrict__ vin,
    float* __restrict__ outS, float* __restrict__ outB,
    int has_bt, int k, int tid)
{
    const int nspans = NN - k;
    // whole-warp early out (uniform across the warp since G divides 32)
    if (((tid & ~31) / G) >= nspans) return;

    const int gid_raw = tid / G;
    const int lig = tid % G;
    const bool lead = (lig == 0) && (gid_raw < nspans);
    const int i = min(gid_raw, nspans - 1);   // clamp dup groups (writes gated by lead)
    const int j = i + k;
    const int rpi = triRow(i);

    // ---- prefetch arc scores + setup BEFORE the wait (off the flag chain) ----
    const float vL = vin[j * NN + i];   // left arc  (head j)
    const float vR = vin[i * NN + j];   // right arc (head i)

    int m  = lig + 1;                   // lane lig handles m = lig+1, lig+1+G, ...
    int q0 = i + m;
    const int A0  = triRow(q0) + (j - q0);                 // tri(q, j)
    const int dA0 = G * (NN - 1 - q0) - (G * (G - 1)) / 2; // A(m+G) - A(m)
    const char* Qb = (const char*)Q;
    int A16   = A0 * 16;
    int B16   = A16 + (NN - 1 - q0) * 16;   // tri(q+1, j) * 16
    int dA16  = dA0 * 16;
    int idx16 = (rpi + m) * 16;             // tri(i, q) * 16

    // ---- gate: poll only what program order can't prove (R12-proven spin) ----
    {
        const bool lastg = (((tid & 31) / G) == (32 / G - 1));
        const bool needs = (gid_raw < nspans) && (CHK || lastg);
        const int f2 = rpi + (NN - i) + (k - 1);   // tri(i+1, j)
        int r = 1;
        if (needs) {
            r = ld_acq_shared(flags + f2);
            if (CHK) r &= ld_acq_shared(flags + rpi + (k - 1));  // tri(i, j-1)
        }
        while (!__all_sync(0xffffffffu, r)) {
            __nanosleep(32);
            r = 1;
            if (needs) {
                r = ld_acq_shared(flags + f2);
                if (CHK) r &= ld_acq_shared(flags + rpi + (k - 1));
            }
        }
    }

    const float NINF = __int_as_float(0xff800000);
    float v00 = NINF, v10 = NINF, v01 = NINF, v11 = NINF;
    int   m00 = NN,   m10 = NN,   m01 = NN,   m11 = NN;

    #pragma unroll 2
    for (; m < k; m += G) {
        const float4 qr = *(const float4*)(Qb + idx16);    // (T00,T11,T10,T01)[i][q]
        const float2 qa = *(const float2*)(Qb + A16);      // (T00,T11)[q][j]
        const float  qb = *(const float*)(Qb + B16 + 12);  // T01[q+1][j]
        const float base = qr.y + qb;
        // preserve reference rounding order: ((s11+s01)+v)+5.0
        float a0  = (base + vL) + 5.0f;
        float a1  = (base + vR) + 5.0f;
        float c01 = qr.w + qa.x;    // T01[i][q] + T00[q][j]
        float c11 = qr.z + qa.y;    // T10[i][q] + T11[q][j]
        if (a0  > v00) { v00 = a0;  m00 = m; }
        if (a1  > v10) { v10 = a1;  m10 = m; }
        if (c01 > v01) { v01 = c01; m01 = m; }
        if (c11 > v11) { v11 = c11; m11 = m; }
        A16 += dA16; B16 += dA16 - 16 * G; dA16 -= 16 * G * G; idx16 += 16 * G;
    }

    if (G > 1) {
        // two-pass: value-only max butterflies, then min-index among ties
        const float o00 = v00, o10 = v10, o01 = v01, o11 = v11;
        #pragma unroll
        for (int off = G / 2; off; off >>= 1) {
            v00 = fmaxf(v00, __shfl_xor_sync(0xffffffffu, v00, off));
            v10 = fmaxf(v10, __shfl_xor_sync(0xffffffffu, v10, off));
            v01 = fmaxf(v01, __shfl_xor_sync(0xffffffffu, v01, off));
            v11 = fmaxf(v11, __shfl_xor_sync(0xffffffffu, v11, off));
        }
        m00 = (o00 == v00) ? m00 : 0x7fffffff;
        m10 = (o10 == v10) ? m10 : 0x7fffffff;
        m01 = (o01 == v01) ? m01 : 0x7fffffff;
        m11 = (o11 == v11) ? m11 : 0x7fffffff;
        #pragma unroll
        for (int off = G / 2; off; off >>= 1) {
            m00 = min(m00, __shfl_xor_sync(0xffffffffu, m00, off));
            m10 = min(m10, __shfl_xor_sync(0xffffffffu, m10, off));
            m01 = min(m01, __shfl_xor_sync(0xffffffffu, m01, off));
            m11 = min(m11, __shfl_xor_sync(0xffffffffu, m11, off));
        }
    }

    if (lead) {
        // ---- m = 0 candidates (share loads with the reference quirk) ----
        const float t11_ii = ((const float4*)Qb)[rpi].y;                   // T11[i][i]
        const float t01_b  = *(const float*)(Qb + (rpi + (NN - i) + (k - 1)) * 16 + 12); // T01[i+1][j]
        const float base0 = t11_ii + t01_b;
        float a0_0 = (base0 + vL) + 5.0f;
        float a1_0 = (base0 + vR) + 5.0f;
        // m=0 is the smallest split: wins value ties (first occurrence)
        if (a0_0 >= v00) { v00 = a0_0; m00 = 0; }
        if (a1_0 >= v10) { v10 = a1_0; m10 = 0; }

        // quirk: (0,1) at q=i sees the (0,0) cell after ONLY the q=i update
        float p000 = fmaxf(a0_0, NEGC);
        const float part00 = (p000 > THRESHC) ? p000 : NEGC;
        if (part00 > v01 || (part00 == v01 && 0 < m01)) { v01 = part00; m01 = 0; }
        // quirk: (1,1) at q=j sees the fully updated (1,0) cell
        const float new10 = (v10 > THRESHC) ? v10 : NEGC;
        if (new10 > v11) { v11 = new10; m11 = k; }

        const float s00 = (v00 > THRESHC) ? v00 : NEGC;
        const float s10 = (v10 > THRESHC) ? v10 : NEGC;
        const float s01 = (v01 > THRESHC) ? v01 : NEGC;
        const float s11 = (v11 > THRESHC) ? v11 : NEGC;

        // ---- publish FIRST (this is the dependency chain) ----
        const int tij = rpi + k;   // tri(i, j)
        Q[tij] = make_float4(s00, s11, s10, s01);
        st_rel_shared(flags + tij, 1);      // release orders the STS above

        // ---- outputs AFTER the release (off the chain), vectorized ----
        const int t00 = (v00 > THRESHC) ? (i + m00) : 0;
        const int t10 = (v10 > THRESHC) ? (i + m10) : 0;
        const int t01 = (v01 > THRESHC) ? (i + m01) : 0;
        const int t11 = (v11 > THRESHC) ? (i + m11) : 0;

        const size_t o = ((size_t)(i * NN + j)) * 4;
        *(float4*)(outS + o) = make_float4(s00, s01, s10, s11);
        if (has_bt) {
            *(float4*)(outB + o) =
                make_float4((float)t00, (float)t01, (float)t10, (float)t11);
        }
    }
}

__global__ void __launch_bounds__(512, 1)
eisner_kernel(const float* __restrict__ vin_all,
              float* __restrict__ out,
              int has_bt, int bt_off)
{
    extern __shared__ float sm[];
    float4* Q = (float4*)sm;                    // TRI cells x 16 B = 132096 B
    int* flags = (int*)(sm + 4 * TRI);          // TRI x 4 B = 33024 B

    const int b = blockIdx.x;
    const float* __restrict__ vin = vin_all + (size_t)b * NN * NN;
    float* __restrict__ outS = out + (size_t)b * NN * NN * 4;
    float* __restrict__ outB = out + (size_t)bt_off + (size_t)b * NN * NN * 4;

    const int tid = threadIdx.x;

    // ---- init (vectorized): all cells NEG, diag = 0; flags 0, diag 1 ----
    {
        float4* sm4 = (float4*)sm;
        const float4 negv = make_float4(NEGC, NEGC, NEGC, NEGC);
        for (int t = tid; t < TRI; t += blockDim.x) sm4[t] = negv;
        int4* fl4 = (int4*)flags;
        const int4 z4 = make_int4(0, 0, 0, 0);
        for (int t = tid; t < TRI / 4; t += blockDim.x) fl4[t] = z4;
    }
    __syncthreads();
    for (int i = tid; i < NN; i += blockDim.x) {
        int d = triRow(i);
        Q[d] = make_float4(0.0f, 0.0f, 0.0f, 0.0f);
        flags[d] = 1;
    }
    // ---- init output (vectorized): scores = NEG, backtrace = 0 ----
    {
        float4* oS4 = (float4*)outS;
        const float4 negv = make_float4(NEGC, NEGC, NEGC, NEGC);
        for (int t = tid; t < NN * NN; t += blockDim.x) oS4[t] = negv;
        if (has_bt) {
            float4* oB4 = (float4*)outB;
            const float4 zv = make_float4(0.0f, 0.0f, 0.0f, 0.0f);
            for (int t = tid; t < NN * NN; t += blockDim.x) oB4[t] = zv;
        }
        // diagonal score cells = 0
        for (int i = tid; i < NN; i += blockDim.x)
            oS4[i * NN + i] = make_float4(0.0f, 0.0f, 0.0f, 0.0f);
    }
    __syncthreads();   // single block-wide barrier; rest is dataflow-synced

    // G policy: k<=12:G1, <=24:G2, <=64:G4, <=96:G8, <=112:G16, else G32.
    // CHK (check both producer flags) at G-transition steps only.
    for (int k = 1; k <= 12; ++k)
        step_body<1,  false>(Q, flags, vin, outS, outB, has_bt, k, tid);
    step_body<2,  true >(Q, flags, vin, outS, outB, has_bt, 13, tid);
    for (int k = 14; k <= 24; ++k)
        step_body<2,  false>(Q, flags, vin, outS, outB, has_bt, k, tid);
    step_body<4,  true >(Q, flags, vin, outS, outB, has_bt, 25, tid);
    for (int k = 26; k <= 64; ++k)
        step_body<4,  false>(Q, flags, vin, outS, outB, has_bt, k, tid);
    step_body<8,  true >(Q, flags, vin, outS, outB, has_bt, 65, tid);
    for (int k = 66; k <= 96; ++k)
        step_body<8,  false>(Q, flags, vin, outS, outB, has_bt, k, tid);
    step_body<16, true >(Q, flags, vin, outS, outB, has_bt, 97, tid);
    for (int k = 98; k <= 112; ++k)
        step_body<16, false>(Q, flags, vin, outS, outB, has_bt, k, tid);
    step_body<32, true >(Q, flags, vin, outS, outB, has_bt, 113, tid);
    for (int k = 114; k < NN; ++k)
        step_body<32, false>(Q, flags, vin, outS, outB, has_bt, k, tid);
}

extern "C" void kernel_launch(void* const* d_in, const int* in_sizes, int n_in,
                              void* d_out, int out_size)
{
    const float* vin = (const float*)d_in[0];
    float* out = (float*)d_out;
    const int B = in_sizes[0] / (NN * NN);          // 64
    const int score_elems = B * NN * NN * 4;        // scores region size
    const int has_bt = (out_size >= 2 * score_elems) ? 1 : 0;

    const int smem_bytes = 4 * TRI * sizeof(float) + TRI * sizeof(int); // 165120 B
    cudaFuncSetAttribute(eisner_kernel,
                         cudaFuncAttributeMaxDynamicSharedMemorySize, smem_bytes);
    eisner_kernel<<<B, 512, smem_bytes>>>(vin, out, has_bt, score_elems);
}

// round 17
// speedup vs baseline: 1.7707x; 1.0056x over previous
#include <cuda_runtime.h>

#define NN 128
#define TRI (NN * (NN + 1) / 2)   // 8256 cells per triangular table

__device__ __forceinline__ int triRow(int a) {
    return a * (2 * NN - a + 1) / 2;   // index of cell (a,a) in triangular packing
}

#define NEGC    (-9999.0f)
#define THRESHC (-9000.0f)

__device__ __forceinline__ int ld_acq_shared(const int* p) {
    int v;
    unsigned a = (unsigned)__cvta_generic_to_shared(p);
    asm volatile("ld.acquire.cta.shared.b32 %0, [%1];" : "=r"(v) : "r"(a) : "memory");
    return v;
}
__device__ __forceinline__ void st_rel_shared(int* p, int v) {
    unsigned a = (unsigned)__cvta_generic_to_shared(p);
    asm volatile("st.release.cta.shared.b32 [%0], %1;" :: "r"(a), "r"(v) : "memory");
}

// Chart storage: one float4 per triangular cell:
//   Q[c] = (T00[c], T11[c], T10[c], T01[c])
// flags[c] = 1 once cell c is written (diag cells pre-set).

// One DP step for span width k, G lanes cooperating per span.
// Sync: program order covers intra-warp deps; only the last group of each
// warp polls its cross-warp flag, except at G-transition steps (CHK).
// Spin: whole-warp poll with immediate nanosleep (R10/R12-proven optimum).
// Loop: branchless argmax (SEL pred-as-data + FMNMX) — 4-cyc carried chains.
template<int G, bool CHK>
__device__ __forceinline__ void step_body(
    float4* __restrict__ Q, int* __restrict__ flags,
    const float* __restrict__ vin,
    float* __restrict__ outS, float* __restrict__ outB,
    int has_bt, int k, int tid)
{
    const int nspans = NN - k;
    // whole-warp early out (uniform across the warp since G divides 32)
    if (((tid & ~31) / G) >= nspans) return;

    const int gid_raw = tid / G;
    const int lig = tid % G;
    const bool lead = (lig == 0) && (gid_raw < nspans);
    const int i = min(gid_raw, nspans - 1);   // clamp dup groups (writes gated by lead)
    const int j = i + k;
    const int rpi = triRow(i);

    // ---- prefetch arc scores + setup BEFORE the wait (off the flag chain) ----
    const float vL = vin[j * NN + i];   // left arc  (head j)
    const float vR = vin[i * NN + j];   // right arc (head i)

    int m  = lig + 1;                   // lane lig handles m = lig+1, lig+1+G, ...
    int q0 = i + m;
    const int A0  = triRow(q0) + (j - q0);                 // tri(q, j)
    const int dA0 = G * (NN - 1 - q0) - (G * (G - 1)) / 2; // A(m+G) - A(m)
    const char* Qb = (const char*)Q;
    int A16   = A0 * 16;
    int B16   = A16 + (NN - 1 - q0) * 16;   // tri(q+1, j) * 16
    int dA16  = dA0 * 16;
    int idx16 = (rpi + m) * 16;             // tri(i, q) * 16

    // ---- gate: poll only what program order can't prove (R12-proven spin) ----
    {
        const bool lastg = (((tid & 31) / G) == (32 / G - 1));
        const bool needs = (gid_raw < nspans) && (CHK || lastg);
        const int f2 = rpi + (NN - i) + (k - 1);   // tri(i+1, j)
        int r = 1;
        if (needs) {
            r = ld_acq_shared(flags + f2);
            if (CHK) r &= ld_acq_shared(flags + rpi + (k - 1));  // tri(i, j-1)
        }
        while (!__all_sync(0xffffffffu, r)) {
            __nanosleep(32);
            r = 1;
            if (needs) {
                r = ld_acq_shared(flags + f2);
                if (CHK) r &= ld_acq_shared(flags + rpi + (k - 1));
            }
        }
    }

    const float NINF = __int_as_float(0xff800000);
    float v00 = NINF, v10 = NINF, v01 = NINF, v11 = NINF;
    int   m00 = NN,   m10 = NN,   m01 = NN,   m11 = NN;

    #pragma unroll 2
    for (; m < k; m += G) {
        const float4 qr = *(const float4*)(Qb + idx16);    // (T00,T11,T10,T01)[i][q]
        const float2 qa = *(const float2*)(Qb + A16);      // (T00,T11)[q][j]
        const float  qb = *(const float*)(Qb + B16 + 12);  // T01[q+1][j]
        const float base = qr.y + qb;
        // preserve reference rounding order: ((s11+s01)+v)+5.0
        float a0  = (base + vL) + 5.0f;
        float a1  = (base + vR) + 5.0f;
        float c01 = qr.w + qa.x;    // T01[i][q] + T00[q][j]
        float c11 = qr.z + qa.y;    // T10[i][q] + T11[q][j]
        // branchless argmax: strict > keeps earliest m on ties (exact ref)
        m00 = (a0  > v00) ? m : m00;  v00 = fmaxf(v00, a0);
        m10 = (a1  > v10) ? m : m10;  v10 = fmaxf(v10, a1);
        m01 = (c01 > v01) ? m : m01;  v01 = fmaxf(v01, c01);
        m11 = (c11 > v11) ? m : m11;  v11 = fmaxf(v11, c11);
        A16 += dA16; B16 += dA16 - 16 * G; dA16 -= 16 * G * G; idx16 += 16 * G;
    }

    if (G > 1) {
        // two-pass: value-only max butterflies, then min-index among ties
        const float o00 = v00, o10 = v10, o01 = v01, o11 = v11;
        #pragma unroll
        for (int off = G / 2; off; off >>= 1) {
            v00 = fmaxf(v00, __shfl_xor_sync(0xffffffffu, v00, off));
            v10 = fmaxf(v10, __shfl_xor_sync(0xffffffffu, v10, off));
            v01 = fmaxf(v01, __shfl_xor_sync(0xffffffffu, v01, off));
            v11 = fmaxf(v11, __shfl_xor_sync(0xffffffffu, v11, off));
        }
        m00 = (o00 == v00) ? m00 : 0x7fffffff;
        m10 = (o10 == v10) ? m10 : 0x7fffffff;
        m01 = (o01 == v01) ? m01 : 0x7fffffff;
        m11 = (o11 == v11) ? m11 : 0x7fffffff;
        #pragma unroll
        for (int off = G / 2; off; off >>= 1) {
            m00 = min(m00, __shfl_xor_sync(0xffffffffu, m00, off));
            m10 = min(m10, __shfl_xor_sync(0xffffffffu, m10, off));
            m01 = min(m01, __shfl_xor_sync(0xffffffffu, m01, off));
            m11 = min(m11, __shfl_xor_sync(0xffffffffu, m11, off));
        }
    }

    if (lead) {
        // ---- m = 0 candidates (share loads with the reference quirk) ----
        const float t11_ii = ((const float4*)Qb)[rpi].y;                   // T11[i][i]
        const float t01_b  = *(const float*)(Qb + (rpi + (NN - i) + (k - 1)) * 16 + 12); // T01[i+1][j]
        const float base0 = t11_ii + t01_b;
        float a0_0 = (base0 + vL) + 5.0f;
        float a1_0 = (base0 + vR) + 5.0f;
        // m=0 is the smallest split: wins value ties (first occurrence)
        if (a0_0 >= v00) { v00 = a0_0; m00 = 0; }
        if (a1_0 >= v10) { v10 = a1_0; m10 = 0; }

        // quirk: (0,1) at q=i sees the (0,0) cell after ONLY the q=i update
        float p000 = fmaxf(a0_0, NEGC);
        const float part00 = (p000 > THRESHC) ? p000 : NEGC;
        if (part00 > v01 || (part00 == v01 && 0 < m01)) { v01 = part00; m01 = 0; }
        // quirk: (1,1) at q=j sees the fully updated (1,0) cell
        const float new10 = (v10 > THRESHC) ? v10 : NEGC;
        if (new10 > v11) { v11 = new10; m11 = k; }

        const float s00 = (v00 > THRESHC) ? v00 : NEGC;
        const float s10 = (v10 > THRESHC) ? v10 : NEGC;
        const float s01 = (v01 > THRESHC) ? v01 : NEGC;
        const float s11 = (v11 > THRESHC) ? v11 : NEGC;

        // ---- publish FIRST (this is the dependency chain) ----
        const int tij = rpi + k;   // tri(i, j)
        Q[tij] = make_float4(s00, s11, s10, s01);
        st_rel_shared(flags + tij, 1);      // release orders the STS above

        // ---- outputs AFTER the release (off the chain), vectorized ----
        const int t00 = (v00 > THRESHC) ? (i + m00) : 0;
        const int t10 = (v10 > THRESHC) ? (i + m10) : 0;
        const int t01 = (v01 > THRESHC) ? (i + m01) : 0;
        const int t11 = (v11 > THRESHC) ? (i + m11) : 0;

        const size_t o = ((size_t)(i * NN + j)) * 4;
        *(float4*)(outS + o) = make_float4(s00, s01, s10, s11);
        if (has_bt) {
            *(float4*)(outB + o) =
                make_float4((float)t00, (float)t01, (float)t10, (float)t11);
        }
    }
}

__global__ void __launch_bounds__(512, 1)
eisner_kernel(const float* __restrict__ vin_all,
              float* __restrict__ out,
              int has_bt, int bt_off)
{
    extern __shared__ float sm[];
    float4* Q = (float4*)sm;                    // TRI cells x 16 B = 132096 B
    int* flags = (int*)(sm + 4 * TRI);          // TRI x 4 B = 33024 B

    const int b = blockIdx.x;
    const float* __restrict__ vin = vin_all + (size_t)b * NN * NN;
    float* __restrict__ outS = out + (size_t)b * NN * NN * 4;
    float* __restrict__ outB = out + (size_t)bt_off + (size_t)b * NN * NN * 4;

    const int tid = threadIdx.x;

    // ---- init (vectorized): all cells NEG, diag = 0; flags 0, diag 1 ----
    {
        float4* sm4 = (float4*)sm;
        const float4 negv = make_float4(NEGC, NEGC, NEGC, NEGC);
        for (int t = tid; t < TRI; t += blockDim.x) sm4[t] = negv;
        int4* fl4 = (int4*)flags;
        const int4 z4 = make_int4(0, 0, 0, 0);
        for (int t = tid; t < TRI / 4; t += blockDim.x) fl4[t] = z4;
    }
    __syncthreads();
    for (int i = tid; i < NN; i += blockDim.x) {
        int d = triRow(i);
        Q[d] = make_float4(0.0f, 0.0f, 0.0f, 0.0f);
        flags[d] = 1;
    }
    // ---- init output (vectorized): scores = NEG, backtrace = 0 ----
    {
        float4* oS4 = (float4*)outS;
        const float4 negv = make_float4(NEGC, NEGC, NEGC, NEGC);
        for (int t = tid; t < NN * NN; t += blockDim.x) oS4[t] = negv;
        if (has_bt) {
            float4* oB4 = (float4*)outB;
            const float4 zv = make_float4(0.0f, 0.0f, 0.0f, 0.0f);
            for (int t = tid; t < NN * NN; t += blockDim.x) oB4[t] = zv;
        }
        // diagonal score cells = 0
        for (int i = tid; i < NN; i += blockDim.x)
            oS4[i * NN + i] = make_float4(0.0f, 0.0f, 0.0f, 0.0f);
    }
    __syncthreads();   // single block-wide barrier; rest is dataflow-synced

    // G policy: k<=12:G1, <=24:G2, <=64:G4, <=96:G8, <=112:G16, else G32.
    // CHK (check both producer flags) at G-transition steps only.
    for (int k = 1; k <= 12; ++k)
        step_body<1,  false>(Q, flags, vin, outS, outB, has_bt, k, tid);
    step_body<2,  true >(Q, flags, vin, outS, outB, has_bt, 13, tid);
    for (int k = 14; k <= 24; ++k)
        step_body<2,  false>(Q, flags, vin, outS, outB, has_bt, k, tid);
    step_body<4,  true >(Q, flags, vin, outS, outB, has_bt, 25, tid);
    for (int k = 26; k <= 64; ++k)
        step_body<4,  false>(Q, flags, vin, outS, outB, has_bt, k, tid);
    step_body<8,  true >(Q, flags, vin, outS, outB, has_bt, 65, tid);
    for (int k = 66; k <= 96; ++k)
        step_body<8,  false>(Q, flags, vin, outS, outB, has_bt, k, tid);
    step_body<16, true >(Q, flags, vin, outS, outB, has_bt, 97, tid);
    for (int k = 98; k <= 112; ++k)
        step_body<16, false>(Q, flags, vin, outS, outB, has_bt, k, tid);
    step_body<32, true >(Q, flags, vin, outS, outB, has_bt, 113, tid);
    for (int k = 114; k < NN; ++k)
        step_body<32, false>(Q, flags, vin, outS, outB, has_bt, k, tid);
}

extern "C" void kernel_launch(void* const* d_in, const int* in_sizes, int n_in,
                              void* d_out, int out_size)
{
    const float* vin = (const float*)d_in[0];
    float* out = (float*)d_out;
    const int B = in_sizes[0] / (NN * NN);          // 64
    const int score_elems = B * NN * NN * 4;        // scores region size
    const int has_bt = (out_size >= 2 * score_elems) ? 1 : 0;

    const int smem_bytes = 4 * TRI * sizeof(float) + TRI * sizeof(int); // 165120 B
    cudaFuncSetAttribute(eisner_kernel,
                         cudaFuncAttributeMaxDynamicSharedMemorySize, smem_bytes);
    eisner_kernel<<<B, 512, smem_bytes>>>(vin, out, has_bt, score_elems);
}